// round 4
// baseline (speedup 1.0000x reference)
#include <cuda_runtime.h>
#include <cuda_bf16.h>
#include <stdint.h>

// Problem constants (fixed by setup_inputs)
#define NN     256
#define CC     3
#define TT     300
#define VV     25
#define MM     2
#define DD     256
#define KK     5
#define TOPK   64
#define NROWS  (NN*MM*TT)        // 153600
#define VMVM   (VV*MM)           // 50
#define SELSZ  (NN*CC*TOPK*VMVM) // 2457600
#define EPSF   1e-8f

// ---------------- scratch (device globals; no allocation allowed) ----------------
__device__ float g_sums[KK*DD];
__device__ float g_counts[KK];
__device__ float g_mean[KK*DD];
__device__ float g_inter[KK];
__device__ float g_Sb;
__device__ float g_Sw;
__device__ float g_score[NROWS];   // per-row frame score (written non-atomically)

// ---------------- kernel 0: zero accumulators (only the atomically-updated ones) ----------------
__global__ void k_zero() {
    int i = blockIdx.x * blockDim.x + threadIdx.x;
    if (i < KK*DD) g_sums[i] = 0.f;
    if (i < KK)    g_counts[i] = 0.f;
    if (i == 0)    g_Sw = 0.f;
}

// ---------------- kernel 1: segment sums + counts (float4, 4 row-groups) ----------------
// Block = 256 threads = 4 groups x 64. Group g, thread c owns columns [c*4, c*4+4).
// Each group walks rows row0+g, row0+g+4, ... (64 rows per group, 256 per block).
#define ROWS_PER_BLOCK 256
__global__ void k_segsum(const float* __restrict__ xT, const int* __restrict__ labels) {
    const int tid = threadIdx.x;
    const int g   = tid >> 6;          // row group 0..3
    const int c   = tid & 63;          // float4 column index
    const int row0 = blockIdx.x * ROWS_PER_BLOCK;

    float4 acc[KK];
    #pragma unroll
    for (int k = 0; k < KK; k++) acc[k] = make_float4(0.f, 0.f, 0.f, 0.f);
    float cnt[KK] = {0.f, 0.f, 0.f, 0.f, 0.f};

    const float4* x4 = (const float4*)xT;
    #pragma unroll 4
    for (int i = 0; i < ROWS_PER_BLOCK/4; i++) {
        const int r = row0 + i*4 + g;
        const int l = __ldg(&labels[r]);              // broadcast within group
        const float4 v = x4[(size_t)r * (DD/4) + c];
        #pragma unroll
        for (int k = 0; k < KK; k++) {
            if (l == k) {
                acc[k].x += v.x; acc[k].y += v.y;
                acc[k].z += v.z; acc[k].w += v.w;
            }
            if (c == 0 && l == k) cnt[k] += 1.f;
        }
    }
    #pragma unroll
    for (int k = 0; k < KK; k++) {
        float* dst = &g_sums[k*DD + c*4];
        atomicAdd(dst + 0, acc[k].x);
        atomicAdd(dst + 1, acc[k].y);
        atomicAdd(dst + 2, acc[k].z);
        atomicAdd(dst + 3, acc[k].w);
    }
    if (c == 0) {
        #pragma unroll
        for (int k = 0; k < KK; k++) atomicAdd(&g_counts[k], cnt[k]);
    }
}

// ---------------- kernel 2: class means, overall mean, inter, Sb (1 block) ----------------
__global__ void k_classstats() {
    const int d = threadIdx.x;             // 256 threads
    __shared__ float red[DD];
    float mean[KK];
    float tot = 0.f;
    #pragma unroll
    for (int k = 0; k < KK; k++) {
        float s = g_sums[k*DD + d];
        float c = g_counts[k];
        tot += s;
        mean[k] = s / fmaxf(c, 1.f);
        g_mean[k*DD + d] = mean[k];
    }
    const float om = tot / (float)NROWS;
    float interloc[KK];
    #pragma unroll
    for (int k = 0; k < KK; k++) {
        float df = mean[k] - om;
        red[d] = df * df;
        __syncthreads();
        for (int off = DD/2; off > 0; off >>= 1) {
            if (d < off) red[d] += red[d + off];
            __syncthreads();
        }
        interloc[k] = red[0];
        __syncthreads();
    }
    if (d == 0) {
        float sb = 0.f;
        #pragma unroll
        for (int k = 0; k < KK; k++) {
            g_inter[k] = interloc[k];
            sb += g_counts[k] * interloc[k];
        }
        g_Sb = sb;
    }
}

// ---------------- kernel 3: intra per row (float4), Sw, scores ----------------
// warp per row; 8 warps/block; each warp handles ROWS_PER_WARP rows.
#define ROWS_PER_WARP 16
__global__ void k_intra(const float* __restrict__ xT, const int* __restrict__ labels) {
    __shared__ float4 smean[KK*DD/4];      // 5KB
    __shared__ float sinter[KK];
    __shared__ float sSw[8];
    const int tid = threadIdx.x;
    {
        const float4* m4 = (const float4*)g_mean;
        for (int i = tid; i < KK*DD/4; i += blockDim.x) smean[i] = m4[i];
        if (tid < KK) sinter[tid] = g_inter[tid];
    }
    __syncthreads();

    const int lane = tid & 31;
    const int wInB = tid >> 5;
    const int warp = blockIdx.x * 8 + wInB;
    float swAcc = 0.f;

    const float4* x4 = (const float4*)xT;
    #pragma unroll 2
    for (int rr = 0; rr < ROWS_PER_WARP; rr++) {
        const int r = warp * ROWS_PER_WARP + rr;
        const int l = __ldg(&labels[r]);
        const float4* xp = x4 + (size_t)r * (DD/4);
        const float4 a  = xp[lane];
        const float4 b  = xp[lane + 32];
        const float4 ma = smean[l*(DD/4) + lane];
        const float4 mb = smean[l*(DD/4) + lane + 32];
        float s;
        {
            float dx = a.x - ma.x, dy = a.y - ma.y, dz = a.z - ma.z, dw = a.w - ma.w;
            s  = dx*dx + dy*dy + dz*dz + dw*dw;
            dx = b.x - mb.x; dy = b.y - mb.y; dz = b.z - mb.z; dw = b.w - mb.w;
            s += dx*dx + dy*dy + dz*dz + dw*dw;
        }
        #pragma unroll
        for (int off = 16; off > 0; off >>= 1)
            s += __shfl_xor_sync(0xFFFFFFFFu, s, off);
        if (lane == 0) {
            swAcc += s;
            g_score[r] = sinter[l] / (s + EPSF);
        }
    }
    if (lane == 0) sSw[wInB] = swAcc;
    __syncthreads();
    if (tid == 0) {
        float b = 0.f;
        #pragma unroll
        for (int w = 0; w < 8; w++) b += sSw[w];
        atomicAdd(&g_Sw, b);
    }
}

// ---------------- kernel 4 (fused): loss + per-sample top-64 + gather ----------------
// Block n handles sample n: VF[t] = score[n,0,t] + score[n,1,t] (exact /2 skipped:
// ranking-identical to jax mean), top-64 with jax.lax.top_k tie semantics
// (value desc, index asc), indices sorted ascending, then gather from x.
__global__ void k_final(const float* __restrict__ x, float* __restrict__ out_sel,
                        float* __restrict__ out_loss) {
    __shared__ float v[TT];
    __shared__ int   sel[TT];
    __shared__ int   sidx[TOPK];
    const int n = blockIdx.x;
    const int t = threadIdx.x;          // 320 threads
    if (n == 0 && t == 0) out_loss[0] = g_Sw / (g_Sb + EPSF);

    if (t < TT)
        v[t] = g_score[(n*MM + 0)*TT + t] + g_score[(n*MM + 1)*TT + t];
    __syncthreads();
    if (t < TT) {
        const float mv = v[t];
        int cnt = 0;
        #pragma unroll 4
        for (int u = 0; u < TT; u++) {
            const float vu = v[u];
            cnt += (vu > mv) || (vu == mv && u < t);
        }
        sel[t] = (cnt < TOPK) ? 1 : 0;
    }
    __syncthreads();
    if (t < TT && sel[t]) {
        int pos = 0;
        for (int u = 0; u < t; u++) pos += sel[u];
        sidx[pos] = t;
    }
    __syncthreads();

    // gather: per-sample out block [C, TOPK, V*M]
    const float* xn = x + (size_t)n * CC * TT * VMVM;
    float* on = out_sel + (size_t)n * CC * TOPK * VMVM;
    for (int o = t; o < CC*TOPK*VMVM; o += blockDim.x) {
        const int vm = o % VMVM;
        const int cj = o / VMVM;
        const int j  = cj % TOPK;
        const int c  = cj / TOPK;
        on[o] = xn[((size_t)c * TT + sidx[j]) * VMVM + vm];
    }
}

// ---------------- launch ----------------
extern "C" void kernel_launch(void* const* d_in, const int* in_sizes, int n_in,
                              void* d_out, int out_size) {
    const float* x  = nullptr;
    const float* xT = nullptr;
    const int* labels = nullptr;
    for (int i = 0; i < n_in; i++) {
        if (in_sizes[i] == NN*CC*TT*VV*MM) x = (const float*)d_in[i];
        else if (in_sizes[i] == NROWS*DD)  xT = (const float*)d_in[i];
        else if (in_sizes[i] == NROWS)     labels = (const int*)d_in[i];
    }
    float* out = (float*)d_out;
    int sel_off = out_size - SELSZ;
    if (sel_off < 0) sel_off = 0;
    float* out_loss = out;
    float* out_sel  = out + sel_off;

    k_zero<<<6, 256>>>();
    k_segsum<<<NROWS/ROWS_PER_BLOCK, 256>>>(xT, labels);
    k_classstats<<<1, 256>>>();
    k_intra<<<NROWS/(8*ROWS_PER_WARP), 256>>>(xT, labels);
    k_final<<<NN, 320>>>(x, out_sel, out_loss);
}

// round 6
// speedup vs baseline: 1.9953x; 1.9953x over previous
#include <cuda_runtime.h>
#include <cuda_bf16.h>
#include <stdint.h>

// Problem constants (fixed by setup_inputs)
#define NN     256
#define CC     3
#define TT     300
#define VV     25
#define MM     2
#define DD     256
#define KK     5
#define TOPK   64
#define NROWS  (NN*MM*TT)        // 153600
#define VMVM   (VV*MM)           // 50
#define SELSZ  (NN*CC*TOPK*VMVM) // 2457600
#define EPSF   1e-8f

#define ROWS_PER_BLOCK 256
#define NBLK_SEG (NROWS/ROWS_PER_BLOCK)   // 600
#define ROWS_PER_WARP 16
#define NBLK_INTRA (NROWS/(8*ROWS_PER_WARP))  // 1200

// ---------------- scratch (device globals; no allocation allowed) ----------------
__device__ float g_partial[NBLK_SEG][KK*DD];   // per-block class sums (3.07MB)
__device__ float g_cntpart[NBLK_SEG][KK];      // per-block class counts
__device__ float g_sums[KK*DD];
__device__ float g_mean[KK*DD];
__device__ float g_inter[KK];
__device__ float g_Sb;
__device__ float g_swpart[NBLK_INTRA];         // per-block Sw partials
__device__ float g_score[NROWS];               // per-row frame score

// ---------------- kernel 1: per-block segment sums (NO atomics) ----------------
// Block = 256 threads = 4 row-groups x 64 float4-columns.
__global__ void k_segsum(const float* __restrict__ xT, const int* __restrict__ labels) {
    __shared__ float4 s4[256];
    __shared__ float  scnt[4][KK];
    const int tid = threadIdx.x;
    const int g   = tid >> 6;          // row group 0..3
    const int c   = tid & 63;          // float4 column index
    const int row0 = blockIdx.x * ROWS_PER_BLOCK;

    float4 acc[KK];
    #pragma unroll
    for (int k = 0; k < KK; k++) acc[k] = make_float4(0.f, 0.f, 0.f, 0.f);
    float cnt[KK] = {0.f, 0.f, 0.f, 0.f, 0.f};

    const float4* x4 = (const float4*)xT;
    #pragma unroll 4
    for (int i = 0; i < ROWS_PER_BLOCK/4; i++) {
        const int r = row0 + i*4 + g;
        const int l = __ldg(&labels[r]);              // uniform within group
        const float4 v = __ldcs(&x4[(size_t)r * (DD/4) + c]);
        #pragma unroll
        for (int k = 0; k < KK; k++) {
            if (l == k) {
                acc[k].x += v.x; acc[k].y += v.y;
                acc[k].z += v.z; acc[k].w += v.w;
            }
            if (c == 0 && l == k) cnt[k] += 1.f;
        }
    }
    // reduce the 4 groups in shared, one class at a time
    float4* out4 = (float4*)&g_partial[blockIdx.x][0];   // 320 float4 per block row
    #pragma unroll
    for (int k = 0; k < KK; k++) {
        s4[tid] = acc[k];
        __syncthreads();
        if (tid < 64) {
            float4 a = s4[tid], b = s4[64+tid], cc2 = s4[128+tid], d = s4[192+tid];
            float4 r;
            r.x = a.x + b.x + cc2.x + d.x;
            r.y = a.y + b.y + cc2.y + d.y;
            r.z = a.z + b.z + cc2.z + d.z;
            r.w = a.w + b.w + cc2.w + d.w;
            out4[k*(DD/4) + tid] = r;
        }
        __syncthreads();
    }
    if (c == 0) {
        #pragma unroll
        for (int k = 0; k < KK; k++) scnt[g][k] = cnt[k];
    }
    __syncthreads();
    if (tid < KK)
        g_cntpart[blockIdx.x][tid] =
            scnt[0][tid] + scnt[1][tid] + scnt[2][tid] + scnt[3][tid];
}

// ---------------- kernel 1b: fold 600 partials -> g_sums ----------------
// 10 blocks x 256 threads; thread = (c4 in 0..31, chunk 0..7); each sums 75 partials.
__global__ void k_reduce() {
    __shared__ float4 s4[256];
    const int tid = threadIdx.x;
    const int c4    = tid & 31;
    const int chunk = tid >> 5;
    const int col = blockIdx.x * 32 + c4;        // float4 column (320 total)
    const float4* p4 = (const float4*)&g_partial[0][0];
    float4 a = make_float4(0.f, 0.f, 0.f, 0.f);
    const int b0 = chunk * (NBLK_SEG/8);
    #pragma unroll 5
    for (int b = b0; b < b0 + NBLK_SEG/8; b++) {
        const float4 v = p4[(size_t)b * 320 + col];
        a.x += v.x; a.y += v.y; a.z += v.z; a.w += v.w;
    }
    s4[tid] = a;
    __syncthreads();
    if (chunk == 0) {
        float4 r = s4[c4];
        #pragma unroll
        for (int j = 1; j < 8; j++) {
            const float4 v = s4[c4 + 32*j];
            r.x += v.x; r.y += v.y; r.z += v.z; r.w += v.w;
        }
        ((float4*)g_sums)[col] = r;
    }
}

// ---------------- kernel 2: counts, class means, overall mean, inter, Sb ----------------
__global__ void k_classstats() {
    const int d = threadIdx.x;             // 256 threads
    __shared__ float red[DD];
    __shared__ float s_counts[KK];
    // counts: warp k reduces class k over 600 blocks
    {
        const int w = d >> 5, lane = d & 31;
        if (w < KK) {
            float s = 0.f;
            for (int b = lane; b < NBLK_SEG; b += 32) s += g_cntpart[b][w];
            #pragma unroll
            for (int off = 16; off > 0; off >>= 1)
                s += __shfl_xor_sync(0xFFFFFFFFu, s, off);
            if (lane == 0) s_counts[w] = s;
        }
    }
    __syncthreads();

    float mean[KK];
    float tot = 0.f;
    #pragma unroll
    for (int k = 0; k < KK; k++) {
        float s = g_sums[k*DD + d];
        tot += s;
        mean[k] = s / fmaxf(s_counts[k], 1.f);
        g_mean[k*DD + d] = mean[k];
    }
    const float om = tot / (float)NROWS;
    float interloc[KK];
    #pragma unroll
    for (int k = 0; k < KK; k++) {
        float df = mean[k] - om;
        red[d] = df * df;
        __syncthreads();
        for (int off = DD/2; off > 0; off >>= 1) {
            if (d < off) red[d] += red[d + off];
            __syncthreads();
        }
        interloc[k] = red[0];
        __syncthreads();
    }
    if (d == 0) {
        float sb = 0.f;
        #pragma unroll
        for (int k = 0; k < KK; k++) {
            g_inter[k] = interloc[k];
            sb += s_counts[k] * interloc[k];
        }
        g_Sb = sb;
    }
}

// ---------------- kernel 3: intra per row (float4), Sw partials, scores ----------------
__global__ void k_intra(const float* __restrict__ xT, const int* __restrict__ labels) {
    __shared__ float4 smean[KK*DD/4];      // 5KB
    __shared__ float sinter[KK];
    __shared__ float sSw[8];
    const int tid = threadIdx.x;
    {
        const float4* m4 = (const float4*)g_mean;
        for (int i = tid; i < KK*DD/4; i += blockDim.x) smean[i] = m4[i];
        if (tid < KK) sinter[tid] = g_inter[tid];
    }
    __syncthreads();

    const int lane = tid & 31;
    const int wInB = tid >> 5;
    const int warp = blockIdx.x * 8 + wInB;
    float swAcc = 0.f;

    const float4* x4 = (const float4*)xT;
    #pragma unroll 2
    for (int rr = 0; rr < ROWS_PER_WARP; rr++) {
        const int r = warp * ROWS_PER_WARP + rr;
        const int l = __ldg(&labels[r]);
        const float4* xp = x4 + (size_t)r * (DD/4);
        const float4 a  = __ldcs(&xp[lane]);
        const float4 b  = __ldcs(&xp[lane + 32]);
        const float4 ma = smean[l*(DD/4) + lane];
        const float4 mb = smean[l*(DD/4) + lane + 32];
        float s;
        {
            float dx = a.x - ma.x, dy = a.y - ma.y, dz = a.z - ma.z, dw = a.w - ma.w;
            s  = dx*dx + dy*dy + dz*dz + dw*dw;
            dx = b.x - mb.x; dy = b.y - mb.y; dz = b.z - mb.z; dw = b.w - mb.w;
            s += dx*dx + dy*dy + dz*dz + dw*dw;
        }
        #pragma unroll
        for (int off = 16; off > 0; off >>= 1)
            s += __shfl_xor_sync(0xFFFFFFFFu, s, off);
        if (lane == 0) {
            swAcc += s;
            g_score[r] = sinter[l] / (s + EPSF);
        }
    }
    if (lane == 0) sSw[wInB] = swAcc;
    __syncthreads();
    if (tid == 0) {
        float b = 0.f;
        #pragma unroll
        for (int w = 0; w < 8; w++) b += sSw[w];
        g_swpart[blockIdx.x] = b;
    }
}

// ---------------- kernel 4 (fused): loss + per-sample top-64 + gather ----------------
__global__ void k_final(const float* __restrict__ x, float* __restrict__ out_sel,
                        float* __restrict__ out_loss) {
    __shared__ float v[TT];
    __shared__ int   sel[TT];
    __shared__ int   sidx[TOPK];
    __shared__ float sred[320];
    const int n = blockIdx.x;
    const int t = threadIdx.x;          // 320 threads

    // block 0: reduce Sw partials -> loss (parallel with its own topk work)
    if (n == 0) {
        float a = 0.f;
        for (int i = t; i < NBLK_INTRA; i += 320) a += g_swpart[i];
        sred[t] = a;
    }

    if (t < TT)
        v[t] = g_score[(n*MM + 0)*TT + t] + g_score[(n*MM + 1)*TT + t];
    __syncthreads();

    if (n == 0 && t < 32) {
        float s2 = 0.f;
        #pragma unroll
        for (int j = t; j < 320; j += 32) s2 += sred[j];
        #pragma unroll
        for (int off = 16; off > 0; off >>= 1)
            s2 += __shfl_xor_sync(0xFFFFFFFFu, s2, off);
        if (t == 0) out_loss[0] = s2 / (g_Sb + EPSF);
    }

    if (t < TT) {
        const float mv = v[t];
        int cnt = 0;
        #pragma unroll 4
        for (int u = 0; u < TT; u++) {
            const float vu = v[u];
            cnt += (vu > mv) || (vu == mv && u < t);
        }
        sel[t] = (cnt < TOPK) ? 1 : 0;
    }
    __syncthreads();
    if (t < TT && sel[t]) {
        int pos = 0;
        for (int u = 0; u < t; u++) pos += sel[u];
        sidx[pos] = t;
    }
    __syncthreads();

    // gather: per-sample out block [C, TOPK, V*M]
    // Scalar stores: out_sel base is out+1 (4-byte aligned only) — no vector casts.
    const float* xn = x + (size_t)n * CC * TT * VMVM;
    float* on = out_sel + (size_t)n * CC * TOPK * VMVM;
    for (int o = t; o < CC*TOPK*VMVM; o += 320) {
        const int vm = o % VMVM;
        const int cj = o / VMVM;
        const int j  = cj % TOPK;
        const int c  = cj / TOPK;
        on[o] = xn[((size_t)c * TT + sidx[j]) * VMVM + vm];
    }
}

// ---------------- launch ----------------
extern "C" void kernel_launch(void* const* d_in, const int* in_sizes, int n_in,
                              void* d_out, int out_size) {
    const float* x  = nullptr;
    const float* xT = nullptr;
    const int* labels = nullptr;
    for (int i = 0; i < n_in; i++) {
        if (in_sizes[i] == NN*CC*TT*VV*MM) x = (const float*)d_in[i];
        else if (in_sizes[i] == NROWS*DD)  xT = (const float*)d_in[i];
        else if (in_sizes[i] == NROWS)     labels = (const int*)d_in[i];
    }
    float* out = (float*)d_out;
    int sel_off = out_size - SELSZ;
    if (sel_off < 0) sel_off = 0;
    float* out_loss = out;
    float* out_sel  = out + sel_off;

    k_segsum<<<NBLK_SEG, 256>>>(xT, labels);
    k_reduce<<<10, 256>>>();
    k_classstats<<<1, 256>>>();
    k_intra<<<NBLK_INTRA, 256>>>(xT, labels);
    k_final<<<NN, 320>>>(x, out_sel, out_loss);
}